// round 7
// baseline (speedup 1.0000x reference)
#include <cuda_runtime.h>

#define TI 128          /* i-extent of a block */
#define TJ 64           /* j-extent of a block (tile split in 2) */
#define NT 512
#define MAX_TILES 64
#define MAX_B (MAX_TILES * (MAX_TILES + 1))   /* 2 blocks per tile-pair */

__device__ double       g_part[MAX_B];
__device__ unsigned int g_count;   // zero at load; last block resets each launch

// SIGMA=1 -> a=1/sqrt(2), c=2a/sqrt(pi).  KEXP = -0.5*log2(e)
#define C_CONST   0.79788456080286536f
#define PA_CONST  0.23174530376899319f   /* 0.3275911 * a */
#define KEXP     -0.72134752044448170f

__device__ __forceinline__ float ex2f(float x)  { float r; asm("ex2.approx.f32 %0,%1;"   : "=f"(r) : "f"(x)); return r; }
__device__ __forceinline__ float rcpf(float x)  { float r; asm("rcp.approx.f32 %0,%1;"   : "=f"(r) : "f"(x)); return r; }
__device__ __forceinline__ float rsqf(float x)  { float r; asm("rsqrt.approx.f32 %0,%1;" : "=f"(r) : "f"(x)); return r; }

template<bool DIAG>
__device__ __forceinline__ float pair_term(
    float rix, float riy, float riz, float qi,
    float uix, float uiy, float uiz,
    const float4& rqj, const float4& ujv,
    bool self)
{
    float dx = rqj.x - rix;
    float dy = rqj.y - riy;
    float dz = rqj.z - riz;
    float rsq = fmaf(dx, dx, fmaf(dy, dy, dz * dz));

    if (DIAG) { if (self) rsq = 1.0f; }      // keep math finite; masked below

    float rinv  = rsqf(rsq);                 // 1 MUFU.RSQ, no refinement
    float rr    = rsq * rinv;                // |r|
    float gauss = ex2f(KEXP * rsq);          // exp(-(a r)^2): 1 FMUL + 1 MUFU.EX2

    // Abramowitz-Stegun 7.1.26 (|err| < 1.5e-7); 'a' folded into PA_CONST
    float t = rcpf(fmaf(PA_CONST, rr, 1.0f));        // 1 FMA + 1 MUFU.RCP
    float poly = fmaf(t, fmaf(t, fmaf(t, fmaf(t, 1.061405429f, -1.453152027f),
                                      1.421413741f), -0.284496736f), 0.254829592f);
    float erfv = fmaf(-t * poly, gauss, 1.0f);

    float rinv2 = rinv * rinv;
    float e1 = erfv * rinv;                          // erf/r
    float e3 = e1 * rinv2;                           // erf/r^3
    float ncg = -C_CONST * gauss;                    // -c*gauss
    float s1 = fmaf(ncg, rinv2, e3);                 // e3 - c*gauss/r^2
    float s2 = (s1 + s1) + (e3 + ncg);               // 3e3 - 2g2 - c*gauss

    float qj  = rqj.w;
    float udi = fmaf(uix, dx, fmaf(uiy, dy, uiz * dz));
    float udj = fmaf(ujv.x, dx, fmaf(ujv.y, dy, ujv.z * dz));
    float uu  = fmaf(uix, ujv.x, fmaf(uiy, ujv.y, uiz * ujv.z));

    float pr = (qi * qj) * e1;                         // qq
    pr = fmaf(-s1, fmaf(qj, udi, -(qi * udj)), pr);    // qu
    pr = fmaf(s1, uu, pr);                             // uu iso
    pr = fmaf(-s2, (udi * udj) * rinv2, pr);           // uu aniso

    if (DIAG) pr = self ? 0.0f : pr;
    return pr;
}

__global__ void __launch_bounds__(NT, 2) pair_kernel(
    const float* __restrict__ q, const float* __restrict__ r,
    const float* __restrict__ u, int n, int tiles, float outscale,
    float* __restrict__ out)
{
    // ---- block -> (tile-pair, j-half) -> (bi, bj, jh) ----
    int p2 = blockIdx.x;
    int pr = p2 >> 1;
    const int jh = p2 & 1;
    int bi = 0;
    while (pr >= tiles - bi) { pr -= tiles - bi; bi++; }
    const int bj = bi + pr;
    const bool diag = (bi == bj);

    __shared__ float4 s_rq[TJ];   // (x, y, z, q)
    __shared__ float4 s_u[TJ];    // (ux, uy, uz, 0)

    const int tx = threadIdx.x;
    const int il = tx & (TI - 1);     // i-lane 0..127
    const int jg = tx >> 7;           // j-group 0..3 (16 j's each)
    const int i  = bi * TI + il;
    const int j0 = bj * TI + jh * TJ;

    if (tx < TJ) {
        int j = j0 + tx;
        float4 v;
        if (j < n) { v.x = r[3*j]; v.y = r[3*j+1]; v.z = r[3*j+2]; v.w = q[j]; }
        else       { v.x = 1.0e7f + (float)j; v.y = 0.f; v.z = 0.f; v.w = 0.f; }
        s_rq[tx] = v;
    } else if (tx < 2 * TJ) {
        int jt = tx - TJ, j = j0 + jt;
        float4 v;
        if (j < n) { v.x = u[3*j]; v.y = u[3*j+1]; v.z = u[3*j+2]; v.w = 0.f; }
        else       { v = make_float4(0.f, 0.f, 0.f, 0.f); }
        s_u[jt] = v;
    }

    float qi = 0.f, rix, riy = 0.f, riz = 0.f, uix = 0.f, uiy = 0.f, uiz = 0.f;
    if (i < n) {
        qi  = q[i];
        rix = r[3*i]; riy = r[3*i+1]; riz = r[3*i+2];
        uix = u[3*i]; uiy = u[3*i+1]; uiz = u[3*i+2];
    } else {
        rix = 2.0e7f + (float)i;   // far, q=u=0 -> zero contribution
    }
    __syncthreads();

    double acc = 0.0;
    const int jbeg = jg * (TJ / 4);    // 16 j's per thread

    if (!diag) {
        #pragma unroll
        for (int g = 0; g < TJ / 4; g += 8) {
            float facc = 0.0f;
            #pragma unroll
            for (int k = 0; k < 8; k++) {
                int jj = jbeg + g + k;
                facc += pair_term<false>(rix, riy, riz, qi, uix, uiy, uiz,
                                         s_rq[jj], s_u[jj], false);
            }
            acc += (double)facc;
        }
    } else {
        #pragma unroll
        for (int g = 0; g < TJ / 4; g += 8) {
            float facc = 0.0f;
            #pragma unroll
            for (int k = 0; k < 8; k++) {
                int jj = jbeg + g + k;
                facc += pair_term<true>(rix, riy, riz, qi, uix, uiy, uiz,
                                        s_rq[jj], s_u[jj], (j0 + jj) == i);
            }
            acc += (double)facc;
        }
        acc *= 0.5;   // diagonal tile double-counts each unordered pair
    }

    // ---- deterministic block reduction ----
    #pragma unroll
    for (int off = 16; off > 0; off >>= 1)
        acc += __shfl_down_sync(0xffffffffu, acc, off);

    __shared__ double warp_s[NT / 32];
    if ((tx & 31) == 0) warp_s[tx >> 5] = acc;
    __syncthreads();

    __shared__ bool isLast;
    if (tx == 0) {
        double s = 0.0;
        #pragma unroll
        for (int w = 0; w < NT / 32; w++) s += warp_s[w];
        g_part[blockIdx.x] = s;
        __threadfence();
        unsigned c = atomicAdd(&g_count, 1u);
        isLast = (c == gridDim.x - 1);
    }
    __syncthreads();

    // ---- last block: final reduction (fixed order -> deterministic) ----
    if (isLast) {
        __threadfence();
        const int nB = gridDim.x;
        double s = 0.0;
        for (int k = tx; k < nB; k += NT) s += g_part[k];

        #pragma unroll
        for (int off = 16; off > 0; off >>= 1)
            s += __shfl_down_sync(0xffffffffu, s, off);

        __shared__ double fin_s[NT / 32];
        if ((tx & 31) == 0) fin_s[tx >> 5] = s;
        __syncthreads();
        if (tx == 0) {
            double tot = 0.0;
            #pragma unroll
            for (int w = 0; w < NT / 32; w++) tot += fin_s[w];
            out[0] = (float)(tot * (double)outscale);
            g_count = 0;   // reset for next graph replay
        }
    }
}

extern "C" void kernel_launch(void* const* d_in, const int* in_sizes, int n_in,
                              void* d_out, int out_size)
{
    const float* q = (const float*)d_in[0];
    const float* r = (const float*)d_in[1];
    const float* u = (const float*)d_in[2];
    float* out = (float*)d_out;

    int n = in_sizes[0];
    int tiles = (n + TI - 1) / TI;
    if (tiles > MAX_TILES) tiles = MAX_TILES;

    int nB = tiles * (tiles + 1);   // 2 j-half blocks per triangular tile-pair
    float outscale = (float)(90.0474 / 6.283185307179586476925286766559);

    pair_kernel<<<nB, NT>>>(q, r, u, n, tiles, outscale, out);
}

// round 8
// speedup vs baseline: 1.0042x; 1.0042x over previous
#include <cuda_runtime.h>

#define TI 128          /* i-extent per block */
#define TJ 32           /* j-extent per block (tile split in 4) */
#define NT 256
#define MAX_TILES 64
#define MAX_B (MAX_TILES * (MAX_TILES + 1) * 2)   /* tilepairs * 4 */

__device__ double       g_part[MAX_B];
__device__ unsigned int g_count;   // zero at load; last block resets each launch

// SIGMA=1 -> a=1/sqrt(2), c=2a/sqrt(pi).  KEXP = -0.5*log2(e)
#define C_CONST   0.79788456080286536f
#define PA_CONST  0.23174530376899319f   /* 0.3275911 * a */
#define KEXP     -0.72134752044448170f

typedef unsigned long long u64;
struct F2 { u64 v; };

__device__ __forceinline__ F2 pack2(float lo, float hi) {
    F2 r; asm("mov.b64 %0,{%1,%2};" : "=l"(r.v) : "f"(lo), "f"(hi)); return r;
}
__device__ __forceinline__ void unpack2(F2 a, float& lo, float& hi) {
    asm("mov.b64 {%0,%1},%2;" : "=f"(lo), "=f"(hi) : "l"(a.v));
}
__device__ __forceinline__ F2 add2(F2 a, F2 b) {
    F2 r; asm("add.rn.f32x2 %0,%1,%2;" : "=l"(r.v) : "l"(a.v), "l"(b.v)); return r;
}
__device__ __forceinline__ F2 mul2(F2 a, F2 b) {
    F2 r; asm("mul.rn.f32x2 %0,%1,%2;" : "=l"(r.v) : "l"(a.v), "l"(b.v)); return r;
}
__device__ __forceinline__ F2 fma2(F2 a, F2 b, F2 c) {
    F2 r; asm("fma.rn.f32x2 %0,%1,%2,%3;" : "=l"(r.v) : "l"(a.v), "l"(b.v), "l"(c.v)); return r;
}
__device__ __forceinline__ float ex2f(float x)  { float r; asm("ex2.approx.f32 %0,%1;"   : "=f"(r) : "f"(x)); return r; }
__device__ __forceinline__ float rcpf(float x)  { float r; asm("rcp.approx.f32 %0,%1;"   : "=f"(r) : "f"(x)); return r; }
__device__ __forceinline__ float rsqf(float x)  { float r; asm("rsqrt.approx.f32 %0,%1;" : "=f"(r) : "f"(x)); return r; }

// scalar erf helper pieces (same ops as the loop -> exact self-cancellation)
__device__ __forceinline__ float erf_part(float rsq, float rinv, float gauss) {
    float rr = rsq * rinv;
    float t  = rcpf(fmaf(PA_CONST, rr, 1.0f));
    float poly = fmaf(t, fmaf(t, fmaf(t, fmaf(t, 1.061405429f, -1.453152027f),
                                      1.421413741f), -0.284496736f), 0.254829592f);
    return fmaf(-(t * poly), gauss, 1.0f);
}

__global__ void __launch_bounds__(NT, 4) pair_kernel(
    const float* __restrict__ q, const float* __restrict__ r,
    const float* __restrict__ u, int n, int tiles, float outscale,
    float* __restrict__ out)
{
    // ---- block -> (tile-pair, j-quarter) ----
    int p4 = blockIdx.x;
    int pr = p4 >> 2;
    const int jh = p4 & 3;
    int bi = 0;
    while (pr >= tiles - bi) { pr -= tiles - bi; bi++; }
    const int bj = bi + pr;
    const bool diag = (bi == bj);

    // SoA j-tile (u64-loadable pairs)
    __shared__ __align__(16) float s_x[TJ], s_y[TJ], s_z[TJ], s_q[TJ];
    __shared__ __align__(16) float s_ux[TJ], s_uy[TJ], s_uz[TJ];

    const int tx = threadIdx.x;
    const int il = tx & (TI - 1);     // i-lane 0..127
    const int jg = tx >> 7;           // j-group 0..1 (16 j's each)
    const int i  = bi * TI + il;
    const int j0 = bj * TI + jh * TJ;

    if (tx < TJ) {
        int j = j0 + tx;
        if (j < n) { s_x[tx] = r[3*j]; s_y[tx] = r[3*j+1]; s_z[tx] = r[3*j+2]; s_q[tx] = q[j]; }
        else       { s_x[tx] = 1.0e7f + (float)j; s_y[tx] = 0.f; s_z[tx] = 0.f; s_q[tx] = 0.f; }
    } else if (tx < 2 * TJ) {
        int jt = tx - TJ, j = j0 + jt;
        if (j < n) { s_ux[jt] = u[3*j]; s_uy[jt] = u[3*j+1]; s_uz[jt] = u[3*j+2]; }
        else       { s_ux[jt] = 0.f; s_uy[jt] = 0.f; s_uz[jt] = 0.f; }
    }

    float qi = 0.f, rix, riy = 0.f, riz = 0.f, uix = 0.f, uiy = 0.f, uiz = 0.f;
    if (i < n) {
        qi  = q[i];
        rix = r[3*i]; riy = r[3*i+1]; riz = r[3*i+2];
        uix = u[3*i]; uiy = u[3*i+1]; uiz = u[3*i+2];
    } else {
        rix = 2.0e7f + (float)i;   // far, q=u=0 -> zero contribution
    }
    __syncthreads();

    // Broadcast-packed per-thread constants
    const F2 nrix2 = pack2(-rix, -rix), nriy2 = pack2(-riy, -riy), nriz2 = pack2(-riz, -riz);
    const F2 uix2  = pack2(uix, uix),   uiy2  = pack2(uiy, uiy),   uiz2  = pack2(uiz, uiz);
    const F2 qi2   = pack2(qi, qi),     nqi2  = pack2(-qi, -qi);
    const F2 NEGC2 = pack2(-C_CONST, -C_CONST);
    const F2 TWO2  = pack2(2.0f, 2.0f);
    const F2 NEG12 = pack2(-1.0f, -1.0f);

    const u64* sx2  = reinterpret_cast<const u64*>(s_x);
    const u64* sy2  = reinterpret_cast<const u64*>(s_y);
    const u64* sz2  = reinterpret_cast<const u64*>(s_z);
    const u64* sq2  = reinterpret_cast<const u64*>(s_q);
    const u64* sux2 = reinterpret_cast<const u64*>(s_ux);
    const u64* suy2 = reinterpret_cast<const u64*>(s_uy);
    const u64* suz2 = reinterpret_cast<const u64*>(s_uz);

    double acc = 0.0;
    const int lp0 = jg * (TJ / 4);    // 8 u64 slots (16 j's) per thread

    #pragma unroll
    for (int o = 0; o < 2; o++) {
        F2 faccp; faccp.v = 0ull;
        #pragma unroll
        for (int k = 0; k < 4; k++) {
            const int lp = lp0 + o * 4 + k;
            F2 xj, yj, zj, qjv, uxj, uyj, uzj;
            xj.v  = sx2[lp];  yj.v  = sy2[lp];  zj.v = sz2[lp]; qjv.v = sq2[lp];
            uxj.v = sux2[lp]; uyj.v = suy2[lp]; uzj.v = suz2[lp];

            F2 dx = add2(xj, nrix2);
            F2 dy = add2(yj, nriy2);
            F2 dz = add2(zj, nriz2);
            F2 rsqp = fma2(dx, dx, fma2(dy, dy, mul2(dz, dz)));

            float r0, r1; unpack2(rsqp, r0, r1);
            // self pair (r==0) only possible on diag blocks; make finite (corrected later)
            r0 = (r0 == 0.0f) ? 1.0f : r0;
            r1 = (r1 == 0.0f) ? 1.0f : r1;

            // scalar MUFU + erf (constants are immediates -> FFMA-imm rt 1)
            float rinv0 = rsqf(r0),          rinv1 = rsqf(r1);
            float g0    = ex2f(r0 * KEXP),   g1    = ex2f(r1 * KEXP);
            float e0    = erf_part(r0, rinv0, g0);
            float e1s   = erf_part(r1, rinv1, g1);

            F2 rinvp  = pack2(rinv0, rinv1);
            F2 gaussp = pack2(g0, g1);
            F2 erfp   = pack2(e0, e1s);

            F2 rinv2p = mul2(rinvp, rinvp);
            F2 e1p    = mul2(erfp, rinvp);
            F2 e3p    = mul2(e1p, rinv2p);
            F2 ncgp   = mul2(gaussp, NEGC2);          // -c*gauss
            F2 s1p    = fma2(ncgp, rinv2p, e3p);      // e3 - c*gauss/r^2
            F2 epn    = add2(e3p, ncgp);
            F2 s2p    = fma2(s1p, TWO2, epn);         // 2*s1 + e3 - c*gauss

            F2 udip = fma2(uix2, dx, fma2(uiy2, dy, mul2(uiz2, dz)));
            F2 udjp = fma2(uxj,  dx, fma2(uyj,  dy, mul2(uzj,  dz)));
            F2 uup  = fma2(uix2, uxj, fma2(uiy2, uyj, mul2(uiz2, uzj)));

            F2 prp  = mul2(mul2(qjv, qi2), e1p);                 // qq
            F2 inn  = fma2(qjv, udip, mul2(nqi2, udjp));         // qj*udi - qi*udj
            F2 ns1p = mul2(s1p, NEG12);
            prp = fma2(ns1p, inn, prp);                          // qu
            prp = fma2(s1p, uup, prp);                           // uu iso
            F2 m2   = mul2(mul2(udip, udjp), rinv2p);
            F2 ns2p = mul2(s2p, NEG12);
            prp = fma2(ns2p, m2, prp);                           // uu aniso

            faccp = add2(faccp, prp);
        }
        float f0, f1; unpack2(faccp, f0, f1);
        acc += (double)(f0 + f1);
    }

    if (diag) {
        // subtract the fake self-pair term (computed with rsq=1, d=0):
        //   qi^2 * e1(1) + s1(1) * (ui.ui), using identical approx ops -> exact cancel
        if ((il >> 4) == (jh * 2 + jg)) {
            float rinvS = rsqf(1.0f);
            float gS    = ex2f(KEXP);
            float eS    = erf_part(1.0f, rinvS, gS);
            float e1S   = eS * rinvS;
            float rinv2S = rinvS * rinvS;
            float e3S   = e1S * rinv2S;
            float s1S   = fmaf(-C_CONST * gS, rinv2S, e3S);
            float uu_i  = fmaf(uix, uix, fmaf(uiy, uiy, uiz * uiz));
            acc -= (double)((qi * qi) * e1S + s1S * uu_i);
        }
        acc *= 0.5;   // diagonal tile double-counts each unordered pair
    }

    // ---- deterministic block reduction ----
    #pragma unroll
    for (int off = 16; off > 0; off >>= 1)
        acc += __shfl_down_sync(0xffffffffu, acc, off);

    __shared__ double warp_s[NT / 32];
    if ((tx & 31) == 0) warp_s[tx >> 5] = acc;
    __syncthreads();

    __shared__ bool isLast;
    if (tx == 0) {
        double s = 0.0;
        #pragma unroll
        for (int w = 0; w < NT / 32; w++) s += warp_s[w];
        g_part[blockIdx.x] = s;
        __threadfence();
        unsigned c = atomicAdd(&g_count, 1u);
        isLast = (c == gridDim.x - 1);
    }
    __syncthreads();

    // ---- last block: final reduction (fixed order -> deterministic) ----
    if (isLast) {
        __threadfence();
        const int nB = gridDim.x;
        double s = 0.0;
        for (int k = tx; k < nB; k += NT) s += g_part[k];

        #pragma unroll
        for (int off = 16; off > 0; off >>= 1)
            s += __shfl_down_sync(0xffffffffu, s, off);

        __shared__ double fin_s[NT / 32];
        if ((tx & 31) == 0) fin_s[tx >> 5] = s;
        __syncthreads();
        if (tx == 0) {
            double tot = 0.0;
            #pragma unroll
            for (int w = 0; w < NT / 32; w++) tot += fin_s[w];
            out[0] = (float)(tot * (double)outscale);
            g_count = 0;   // reset for next graph replay
        }
    }
}

extern "C" void kernel_launch(void* const* d_in, const int* in_sizes, int n_in,
                              void* d_out, int out_size)
{
    const float* q = (const float*)d_in[0];
    const float* r = (const float*)d_in[1];
    const float* u = (const float*)d_in[2];
    float* out = (float*)d_out;

    int n = in_sizes[0];
    int tiles = (n + TI - 1) / TI;
    if (tiles > MAX_TILES) tiles = MAX_TILES;

    int nB = tiles * (tiles + 1) * 2;   // 4 j-quarter blocks per triangular tile-pair
    float outscale = (float)(90.0474 / 6.283185307179586476925286766559);

    pair_kernel<<<nB, NT>>>(q, r, u, n, tiles, outscale, out);
}